// round 13
// baseline (speedup 1.0000x reference)
#include <cuda_runtime.h>
#include <cuda_fp16.h>
#include <cstdint>

// ============================================================================
// y = x @ W_mod^T ; W_mod = W with values*0.1 scattered at flip_idx (last wins)
// R13: W conversion FUSED INTO GEMM (raw f32 W read once; no wh array).
//   K1: winner election + x->f16 (chunk-major swizzled) + bucket-count zero
//   K2: exchange-dedup -> per-(chunk,n_tile) patch buckets
//   K3: GEMM; per chunk: LDG B f32 (prefetched) -> cvt -> STS f16 -> patches
//       -> 8x(ldsm+mma). A via 3-deep TMA bulk pipeline.
// ============================================================================

#define O_DIM  4096
#define I_DIM  4096
#define B_ROWS 256
#define W_ELEMS (O_DIM * I_DIM)
#define X_ELEMS (B_ROWS * I_DIM)
#define NC      32                     // K-chunks of 128

#define SW128(b) ((b) ^ (((b) >> 3) & 0x70))

// x, chunk-major swizzled: [chunk 32][m_tile 2][sub0 16KB | sub1 16KB]
__device__ __align__(16) __half g_xh[X_ELEMS];
// winner tokens; zero at module load; K2's atomicExch restores all-zero
__device__ int g_aux[W_ELEMS];
// patch buckets: [chunk 32][n_tile 64], <=1024 entries each
__device__ int      g_bcnt[2048];
__device__ unsigned g_bdata[2048 * 1024];

// ----------------------------------------------------------------------------
// K1: fused [winner election | x convert | bcnt zero]
// ----------------------------------------------------------------------------
static constexpr int NB_WIN = 977;                 // ceil(1e6/1024), 4 idx/thr
static constexpr int NB_CX  = X_ELEMS / 4 / 256;   // 1024

__global__ void __launch_bounds__(256) stage1_kernel(
    const float4* __restrict__ x, const int* __restrict__ flip, int n) {
    const int bid = blockIdx.x, tid = threadIdx.x;
    if (bid < NB_WIN) {
        const int base = bid * 1024 + tid * 4;
        if (base + 3 < n) {
            const int4 f = *reinterpret_cast<const int4*>(flip + base);
            atomicMax(&g_aux[f.x], base + 1);
            atomicMax(&g_aux[f.y], base + 2);
            atomicMax(&g_aux[f.z], base + 3);
            atomicMax(&g_aux[f.w], base + 4);
        } else {
            for (int k = 0; k < 4; ++k)
                if (base + k < n) atomicMax(&g_aux[flip[base + k]], base + k + 1);
        }
    } else if (bid < NB_WIN + NB_CX) {
        const int i = (bid - NB_WIN) * 256 + tid;
        const int m = i >> 10, kq = (i & 1023) << 2;
        float4 v = __ldcs(x + i);
        uint2 p = make_uint2(
            (uint32_t)__half_as_ushort(__float2half_rn(v.x)) |
            ((uint32_t)__half_as_ushort(__float2half_rn(v.y)) << 16),
            (uint32_t)__half_as_ushort(__float2half_rn(v.z)) |
            ((uint32_t)__half_as_ushort(__float2half_rn(v.w)) << 16));
        const int c = kq >> 7, k0 = kq & 127, sub = k0 >> 6, kk = k0 & 63;
        char* dst = reinterpret_cast<char*>(g_xh)
                  + (size_t)c * 65536 + (m >> 7) * 32768 + sub * 16384
                  + SW128((m & 127) * 128 + kk * 2);
        __stcs(reinterpret_cast<uint2*>(dst), p);
    } else {
        #pragma unroll
        for (int j = 0; j < 8; ++j) g_bcnt[tid * 8 + j] = 0;
    }
}

// ----------------------------------------------------------------------------
// K2: exchange-dedup -> bucket append  (8 idx/thread for MLP)
// ----------------------------------------------------------------------------
__device__ __forceinline__ void emit_patch(int pos, float v) {
    const int o = pos >> 12, i = pos & 4095;
    const int bucket = (i >> 7) * 64 + (o >> 6);
    const int lp = (o & 63) * 128 + (i & 127);          // 13 bits
    const unsigned hb = __half_as_ushort(__float2half_rn(v));
    const int slot = atomicAdd(&g_bcnt[bucket], 1);
    if (slot < 1024)
        g_bdata[bucket * 1024 + slot] = ((unsigned)lp << 16) | hb;
}

__global__ void __launch_bounds__(256) scatter_kernel(
    const int* __restrict__ flip, const float* __restrict__ vals, int n) {
    const int base = (blockIdx.x * 256 + threadIdx.x) * 8;
    if (base + 7 < n) {
        const int4 f0 = *reinterpret_cast<const int4*>(flip + base);
        const int4 f1 = *reinterpret_cast<const int4*>(flip + base + 4);
        int pos[8] = {f0.x, f0.y, f0.z, f0.w, f1.x, f1.y, f1.z, f1.w};
        int old[8];
        #pragma unroll
        for (int k = 0; k < 8; ++k) old[k] = atomicExch(&g_aux[pos[k]], 0);
        #pragma unroll
        for (int k = 0; k < 8; ++k)
            if (old[k]) emit_patch(pos[k], vals[old[k] - 1] * 0.1f);
    } else {
        for (int k = 0; k < 8; ++k)
            if (base + k < n) {
                int p = flip[base + k];
                int o = atomicExch(&g_aux[p], 0);
                if (o) emit_patch(p, vals[o - 1] * 0.1f);
            }
    }
}

// ============================================================================
// K3: GEMM. CTA 128x64, K-chunk 128. A: 3-deep TMA (f16). B: raw f32 LDG
// prefetch -> cvt -> STS f16 (2 buffers) -> patches -> 8 ks of ldsm+mma.
// ============================================================================
static constexpr int A_SUB  = 16384;   // A sub-tile: 128 rows x 128B
static constexpr int A_BUF  = 32768;
static constexpr int SM_A   = 1024;
static constexpr int SM_BF  = SM_A + 3 * A_BUF;        // Bf16: 2 x 16KB
static constexpr int GEMM_SMEM = SM_BF + 2 * 16384;    // 132096

__device__ __forceinline__ uint32_t smem_u32(const void* p) {
    uint32_t a;
    asm("{ .reg .u64 t; cvta.to.shared.u64 t, %1; cvt.u32.u64 %0, t; }"
        : "=r"(a) : "l"(p));
    return a;
}
__device__ __forceinline__ void ldsm4(uint32_t* r, uint32_t addr) {
    asm volatile("ldmatrix.sync.aligned.m8n8.x4.shared.b16 {%0,%1,%2,%3}, [%4];"
                 : "=r"(r[0]), "=r"(r[1]), "=r"(r[2]), "=r"(r[3]) : "r"(addr));
}
__device__ __forceinline__ void mma16816(float* c, const uint32_t* a,
                                         uint32_t b0, uint32_t b1) {
    asm volatile(
        "mma.sync.aligned.m16n8k16.row.col.f32.f16.f16.f32 "
        "{%0,%1,%2,%3}, {%4,%5,%6,%7}, {%8,%9}, {%0,%1,%2,%3};"
        : "+f"(c[0]), "+f"(c[1]), "+f"(c[2]), "+f"(c[3])
        : "r"(a[0]), "r"(a[1]), "r"(a[2]), "r"(a[3]), "r"(b0), "r"(b1));
}

#define MBAR_WAIT(mbar_addr, phase) do {                                         \
    uint32_t _mbar = (uint32_t)(mbar_addr);                                      \
    uint32_t _parity = (uint32_t)(phase);                                        \
    uint32_t _done;                                                              \
    asm volatile(                                                                \
        "{\n\t.reg .pred p;\n\t"                                                 \
        "mbarrier.try_wait.parity.acquire.cta.shared::cta.b64 p, [%1], %2;\n\t"  \
        "selp.b32 %0, 1, 0, p;\n\t}"                                             \
        : "=r"(_done) : "r"(_mbar), "r"(_parity) : "memory");                    \
    if (!_done) {                                                                \
        asm volatile(                                                            \
            "{\n\t.reg .pred P1;\n\t"                                            \
            "WL_%=:\n\t"                                                         \
            "mbarrier.try_wait.parity.acquire.cta.shared::cta.b64 P1, [%0], %1, 0x989680;\n\t" \
            "@P1 bra.uni WD_%=;\n\t"                                             \
            "bra.uni WL_%=;\n\t"                                                 \
            "WD_%=:\n\t}"                                                        \
            :: "r"(_mbar), "r"(_parity) : "memory");                             \
    }                                                                            \
} while (0)

__device__ __forceinline__ void tma_A(uint32_t bufb, uint32_t mbar, int c, int m0) {
    asm volatile("mbarrier.arrive.expect_tx.shared.b64 _, [%0], %1;"
                 :: "r"(mbar), "r"(32768u) : "memory");
    const char* src = reinterpret_cast<const char*>(g_xh)
                    + (size_t)c * 65536 + (m0 >> 7) * 32768;
    asm volatile(
        "cp.async.bulk.shared::cluster.global.mbarrier::complete_tx::bytes "
        "[%0], [%1], %2, [%3];"
        :: "r"(bufb), "l"(src), "r"(32768u), "r"(mbar) : "memory");
}

__global__ void __launch_bounds__(256, 1) gemm_kernel(
    float* __restrict__ y, const float4* __restrict__ wraw) {
    extern __shared__ __align__(1024) char smem[];
    const uint32_t sb = smem_u32(smem);
    const int tid = threadIdx.x, lane = tid & 31, wid = tid >> 5;
    const int wm = wid >> 1, wn = wid & 1;          // warp grid 4(M) x 2(N)
    const int n0 = blockIdx.x * 64;
    const int m0 = blockIdx.y * 128;

    if (tid < 3)
        asm volatile("mbarrier.init.shared.b64 [%0], 1;"
                     :: "r"(sb + tid * 8) : "memory");
    __syncthreads();
    if (tid == 0) {
        tma_A(sb + SM_A + 0 * A_BUF, sb + 0, 0, m0);
        tma_A(sb + SM_A + 1 * A_BUF, sb + 8, 1, m0);
    }

    // B f32 thread mapping: row r = tid>>2 (0..63), part p = tid&3 (32 cols)
    const int r = tid >> 2, p = tid & 3;
    const size_t bbase = (size_t)(n0 + r) * 1024 + (size_t)p * 8;  // float4 idx
    // Bf16 STS targets (within the (p>>1) sub, col block (p&1)*64 bytes)
    const uint32_t bsub = (uint32_t)(p >> 1) * 8192;
    const uint32_t brow_sts = (uint32_t)r * 128 + (uint32_t)(p & 1) * 64;

    float4 breg[8];
    #pragma unroll
    for (int j = 0; j < 8; ++j) breg[j] = __ldcs(wraw + bbase + j);  // chunk 0

    float acc[2][4][4];
    #pragma unroll
    for (int i = 0; i < 2; ++i)
        #pragma unroll
        for (int j = 0; j < 4; ++j)
            #pragma unroll
            for (int q = 0; q < 4; ++q) acc[i][j][q] = 0.f;

    const int rl = lane & 15;
    const uint32_t kh16 = (uint32_t)(lane >> 4) * 16;
    const uint32_t arow0 = (uint32_t)(wm * 32 + rl) * 128;
    const uint32_t arow1 = arow0 + 16 * 128;
    const uint32_t brow0 = (uint32_t)(wn * 32 + rl) * 128;
    const uint32_t brow1 = brow0 + 16 * 128;
    const int nb_base = (n0 >> 6);

    for (int c = 0; c < NC; ++c) {
        const uint32_t bf = sb + SM_BF + (uint32_t)(c & 1) * 16384;

        // convert prefetched B f32 -> f16, STS (4 x 16B per thread)
        #pragma unroll
        for (int j2 = 0; j2 < 4; ++j2) {
            float4 v0 = breg[2 * j2], v1 = breg[2 * j2 + 1];
            uint4 u;
            u.x = (uint32_t)__half_as_ushort(__float2half_rn(v0.x)) |
                  ((uint32_t)__half_as_ushort(__float2half_rn(v0.y)) << 16);
            u.y = (uint32_t)__half_as_ushort(__float2half_rn(v0.z)) |
                  ((uint32_t)__half_as_ushort(__float2half_rn(v0.w)) << 16);
            u.z = (uint32_t)__half_as_ushort(__float2half_rn(v1.x)) |
                  ((uint32_t)__half_as_ushort(__float2half_rn(v1.y)) << 16);
            u.w = (uint32_t)__half_as_ushort(__float2half_rn(v1.z)) |
                  ((uint32_t)__half_as_ushort(__float2half_rn(v1.w)) << 16);
            const uint32_t addr = bf + bsub + SW128(brow_sts + j2 * 16);
            asm volatile("st.shared.v4.b32 [%0], {%1,%2,%3,%4};"
                         :: "r"(addr), "r"(u.x), "r"(u.y), "r"(u.z), "r"(u.w)
                         : "memory");
        }
        __syncthreads();

        // apply patches for (chunk c, this n-tile)
        {
            const int bucket = c * 64 + nb_base;
            const int cnt = min(g_bcnt[bucket], 1024);
            for (int j = tid; j < cnt; j += 256) {
                const unsigned e = g_bdata[bucket * 1024 + j];
                const int lp = e >> 16, col = lp & 127, row = lp >> 7;
                const uint32_t addr = bf + (uint32_t)(col >> 6) * 8192
                                    + SW128((uint32_t)row * 128 + (col & 63) * 2);
                asm volatile("st.shared.u16 [%0], %1;"
                             :: "r"(addr), "h"((unsigned short)(e & 0xFFFF))
                             : "memory");
            }
        }
        __syncthreads();

        // issue A TMA for chunk c+2 (buffer freed: all warps past MMA c-1)
        if (tid == 0 && c + 2 < NC)
            tma_A(sb + SM_A + ((c + 2) % 3) * A_BUF, sb + ((c + 2) % 3) * 8,
                  c + 2, m0);
        // prefetch B f32 for chunk c+1 (latency hides under MMAs below)
        if (c + 1 < NC) {
            const size_t off = bbase + (size_t)(c + 1) * 32;
            #pragma unroll
            for (int j = 0; j < 8; ++j) breg[j] = __ldcs(wraw + off + j);
        }

        MBAR_WAIT(sb + (c % 3) * 8, (c / 3) & 1);
        const uint32_t ab = sb + SM_A + (uint32_t)(c % 3) * A_BUF;

        #pragma unroll
        for (int ks = 0; ks < 8; ++ks) {
            const uint32_t sub_a = ab + (ks >> 2) * A_SUB;
            const uint32_t sub_b = bf + (ks >> 2) * 8192;
            const uint32_t kb = (uint32_t)(ks & 3) * 32 + kh16;
            uint32_t ah[2][4], bh[2][4];
            ldsm4(ah[0], sub_a + SW128(arow0 + kb));
            ldsm4(ah[1], sub_a + SW128(arow1 + kb));
            ldsm4(bh[0], sub_b + SW128(brow0 + kb));
            ldsm4(bh[1], sub_b + SW128(brow1 + kb));
            #pragma unroll
            for (int mi = 0; mi < 2; ++mi)
                #pragma unroll
                for (int nj = 0; nj < 2; ++nj) {
                    mma16816(acc[mi][nj*2+0], ah[mi], bh[nj][0], bh[nj][2]);
                    mma16816(acc[mi][nj*2+1], ah[mi], bh[nj][1], bh[nj][3]);
                }
        }
    }

    #pragma unroll
    for (int mi = 0; mi < 2; ++mi) {
        const int row0 = m0 + wm * 32 + mi * 16 + (lane >> 2);
        #pragma unroll
        for (int nb = 0; nb < 4; ++nb) {
            const int col = n0 + wn * 32 + nb * 8 + (lane & 3) * 2;
            *reinterpret_cast<float2*>(y + (size_t)row0 * O_DIM + col) =
                make_float2(acc[mi][nb][0], acc[mi][nb][1]);
            *reinterpret_cast<float2*>(y + (size_t)(row0 + 8) * O_DIM + col) =
                make_float2(acc[mi][nb][2], acc[mi][nb][3]);
        }
    }
}

// ============================================================================
extern "C" void kernel_launch(void* const* d_in, const int* in_sizes, int n_in,
                              void* d_out, int out_size) {
    const float* x    = (const float*)d_in[0];
    const float* w    = (const float*)d_in[1];
    const int*   flip = (const int*)d_in[2];   // JAX x64 disabled -> int32
    const float* vals = (const float*)d_in[3];
    float*       y    = (float*)d_out;
    const int nflip = in_sizes[2];

    stage1_kernel<<<NB_WIN + NB_CX + 1, 256>>>(
        reinterpret_cast<const float4*>(x), flip, nflip);
    scatter_kernel<<<(nflip + 2047) / 2048, 256>>>(flip, vals, nflip);

    cudaFuncSetAttribute(gemm_kernel, cudaFuncAttributeMaxDynamicSharedMemorySize,
                         GEMM_SMEM);
    gemm_kernel<<<dim3(O_DIM / 64, B_ROWS / 128, 1), 256, GEMM_SMEM>>>(
        y, reinterpret_cast<const float4*>(w));
}

// round 14
// speedup vs baseline: 1.8878x; 1.8878x over previous
#include <cuda_runtime.h>
#include <cuda_fp16.h>
#include <cstdint>

// ============================================================================
// y = x @ W_mod^T ; W_mod = W with values*0.1 scattered at flip_idx (last wins)
// x:[256,4096] f32, W:[4096,4096] f32, flip:[1M] int32, vals:[1M] f32 -> y f32
// R14: R11 architecture (best 87.8us) with 4-buffer TMA pipeline and block
// barrier every 2 chunks (16 syncs instead of 32).
// ============================================================================

#define O_DIM  4096
#define I_DIM  4096
#define B_ROWS 256
#define W_ELEMS (O_DIM * I_DIM)
#define X_ELEMS (B_ROWS * I_DIM)

#define SW128(b) ((b) ^ (((b) >> 3) & 0x70))

// Chunk-major swizzled layouts (K-chunk = 128 cols = 256B, two 128B sub-tiles):
//  g_xh: [chunk 32][m_tile 2][ sub0 16KB | sub1 16KB ]          (64KB/chunk)
//  g_wh: [chunk 32][n_grp 64][ sub0 8KB | sub1 8KB ]            (1MB/chunk)
__device__ __align__(16) __half g_xh[X_ELEMS];
__device__ __align__(16) __half g_wh[W_ELEMS];
// zero at module load; atomicExch in scatter restores all-zero every launch
__device__ int g_aux[W_ELEMS];

// ----------------------------------------------------------------------------
// Stage 1: fused [winner election | x convert | W convert]  (R10-exact)
// ----------------------------------------------------------------------------
static constexpr int NB_WIN = 977;                 // ceil(1e6/1024), 4 idx/thr
static constexpr int NB_CX  = X_ELEMS / 4 / 256;   // 1024
static constexpr int NB_CW  = W_ELEMS / 4 / 256;   // 16384

__global__ void __launch_bounds__(256) stage1_kernel(
    const float4* __restrict__ x, const float4* __restrict__ w,
    const int* __restrict__ flip, int n) {
    const int bid = blockIdx.x, tid = threadIdx.x;
    if (bid < NB_WIN) {
        const int base = bid * 1024 + tid * 4;
        if (base + 3 < n) {
            const int4 f = *reinterpret_cast<const int4*>(flip + base);
            atomicMax(&g_aux[f.x], base + 1);
            atomicMax(&g_aux[f.y], base + 2);
            atomicMax(&g_aux[f.z], base + 3);
            atomicMax(&g_aux[f.w], base + 4);
        } else {
            for (int k = 0; k < 4; ++k)
                if (base + k < n) atomicMax(&g_aux[flip[base + k]], base + k + 1);
        }
    } else if (bid < NB_WIN + NB_CX) {
        const int i = (bid - NB_WIN) * 256 + tid;
        const int m = i >> 10, kq = (i & 1023) << 2;      // 4 k-elems
        float4 v = __ldcs(x + i);
        uint2 p = make_uint2(
            (uint32_t)__half_as_ushort(__float2half_rn(v.x)) |
            ((uint32_t)__half_as_ushort(__float2half_rn(v.y)) << 16),
            (uint32_t)__half_as_ushort(__float2half_rn(v.z)) |
            ((uint32_t)__half_as_ushort(__float2half_rn(v.w)) << 16));
        const int c = kq >> 7, k0 = kq & 127, sub = k0 >> 6, kk = k0 & 63;
        char* dst = reinterpret_cast<char*>(g_xh)
                  + (size_t)c * 65536 + (m >> 7) * 32768 + sub * 16384
                  + SW128((m & 127) * 128 + kk * 2);
        __stcs(reinterpret_cast<uint2*>(dst), p);
    } else {
        const int i = (bid - NB_WIN - NB_CX) * 256 + tid;
        const int o = i >> 10, kq = (i & 1023) << 2;
        float4 v = __ldcs(w + i);
        uint2 p = make_uint2(
            (uint32_t)__half_as_ushort(__float2half_rn(v.x)) |
            ((uint32_t)__half_as_ushort(__float2half_rn(v.y)) << 16),
            (uint32_t)__half_as_ushort(__float2half_rn(v.z)) |
            ((uint32_t)__half_as_ushort(__float2half_rn(v.w)) << 16));
        const int c = kq >> 7, k0 = kq & 127, sub = k0 >> 6, kk = k0 & 63;
        char* dst = reinterpret_cast<char*>(g_wh)
                  + (size_t)c * 1048576 + (o >> 6) * 16384 + sub * 8192
                  + SW128((o & 63) * 128 + kk * 2);
        __stcs(reinterpret_cast<uint2*>(dst), p);
    }
}

// ----------------------------------------------------------------------------
// Stage 2: exchange-scatter (8 idx/thread, R10-exact)
// ----------------------------------------------------------------------------
__device__ __forceinline__ void scatter_one(int pos, float v) {
    const int o = pos >> 12, k = pos & 4095;
    const int c = k >> 7, k0 = k & 127, sub = k0 >> 6, kk = k0 & 63;
    char* dst = reinterpret_cast<char*>(g_wh)
              + (size_t)c * 1048576 + (o >> 6) * 16384 + sub * 8192
              + SW128((o & 63) * 128 + kk * 2);
    *reinterpret_cast<__half*>(dst) = __float2half_rn(v);
}

__global__ void __launch_bounds__(256) scatter_kernel(
    const int* __restrict__ flip, const float* __restrict__ vals, int n) {
    const int base = (blockIdx.x * 256 + threadIdx.x) * 8;
    if (base + 7 < n) {
        const int4 f0 = *reinterpret_cast<const int4*>(flip + base);
        const int4 f1 = *reinterpret_cast<const int4*>(flip + base + 4);
        int pos[8] = {f0.x, f0.y, f0.z, f0.w, f1.x, f1.y, f1.z, f1.w};
        int old[8];
        #pragma unroll
        for (int k = 0; k < 8; ++k) old[k] = atomicExch(&g_aux[pos[k]], 0);
        #pragma unroll
        for (int k = 0; k < 8; ++k)
            if (old[k]) scatter_one(pos[k], vals[old[k] - 1] * 0.1f);
    } else {
        for (int k = 0; k < 8; ++k)
            if (base + k < n) {
                int p = flip[base + k];
                int o = atomicExch(&g_aux[p], 0);
                if (o) scatter_one(p, vals[o - 1] * 0.1f);
            }
    }
}

// ============================================================================
// Stage 3: GEMM. CTA 128x64, K-chunk 128, 4-deep TMA pipeline, block barrier
// every 2 chunks with dual reissue.
// ============================================================================
static constexpr int A_SUB = 16384;   // A sub-tile: 128 rows x 128B
static constexpr int B_OFF = 32768;
static constexpr int B_SUB = 8192;    // B sub-tile: 64 rows x 128B
static constexpr int BUF   = 49152;
static constexpr int SM_TILES = 1024;
static constexpr int GEMM_SMEM = SM_TILES + 4 * BUF;   // 197632
static constexpr int NC    = I_DIM / 128;   // 32 chunks

__device__ __forceinline__ uint32_t smem_u32(const void* p) {
    uint32_t a;
    asm("{ .reg .u64 t; cvta.to.shared.u64 t, %1; cvt.u32.u64 %0, t; }"
        : "=r"(a) : "l"(p));
    return a;
}
__device__ __forceinline__ void ldsm4(uint32_t* r, uint32_t addr) {
    asm volatile("ldmatrix.sync.aligned.m8n8.x4.shared.b16 {%0,%1,%2,%3}, [%4];"
                 : "=r"(r[0]), "=r"(r[1]), "=r"(r[2]), "=r"(r[3]) : "r"(addr));
}
__device__ __forceinline__ void mma16816(float* c, const uint32_t* a,
                                         uint32_t b0, uint32_t b1) {
    asm volatile(
        "mma.sync.aligned.m16n8k16.row.col.f32.f16.f16.f32 "
        "{%0,%1,%2,%3}, {%4,%5,%6,%7}, {%8,%9}, {%0,%1,%2,%3};"
        : "+f"(c[0]), "+f"(c[1]), "+f"(c[2]), "+f"(c[3])
        : "r"(a[0]), "r"(a[1]), "r"(a[2]), "r"(a[3]), "r"(b0), "r"(b1));
}

#define MBAR_WAIT(mbar_addr, phase) do {                                         \
    uint32_t _mbar = (uint32_t)(mbar_addr);                                      \
    uint32_t _parity = (uint32_t)(phase);                                        \
    uint32_t _done;                                                              \
    asm volatile(                                                                \
        "{\n\t.reg .pred p;\n\t"                                                 \
        "mbarrier.try_wait.parity.acquire.cta.shared::cta.b64 p, [%1], %2;\n\t"  \
        "selp.b32 %0, 1, 0, p;\n\t}"                                             \
        : "=r"(_done) : "r"(_mbar), "r"(_parity) : "memory");                    \
    if (!_done) {                                                                \
        asm volatile(                                                            \
            "{\n\t.reg .pred P1;\n\t"                                            \
            "WL_%=:\n\t"                                                         \
            "mbarrier.try_wait.parity.acquire.cta.shared::cta.b64 P1, [%0], %1, 0x989680;\n\t" \
            "@P1 bra.uni WD_%=;\n\t"                                             \
            "bra.uni WL_%=;\n\t"                                                 \
            "WD_%=:\n\t}"                                                        \
            :: "r"(_mbar), "r"(_parity) : "memory");                             \
    }                                                                            \
} while (0)

// Issue A(32KB) + B(16KB) bulk copies for chunk c into buffer (single thread).
__device__ __forceinline__ void tma_chunk(uint32_t bufb, uint32_t mbar,
                                          int c, int m0, int n0) {
    asm volatile("mbarrier.arrive.expect_tx.shared.b64 _, [%0], %1;"
                 :: "r"(mbar), "r"(49152u) : "memory");
    const char* srcA = reinterpret_cast<const char*>(g_xh)
                     + (size_t)c * 65536 + (m0 >> 7) * 32768;
    const char* srcB = reinterpret_cast<const char*>(g_wh)
                     + (size_t)c * 1048576 + (n0 >> 6) * 16384;
    asm volatile(
        "cp.async.bulk.shared::cluster.global.mbarrier::complete_tx::bytes "
        "[%0], [%1], %2, [%3];"
        :: "r"(bufb), "l"(srcA), "r"(32768u), "r"(mbar) : "memory");
    asm volatile(
        "cp.async.bulk.shared::cluster.global.mbarrier::complete_tx::bytes "
        "[%0], [%1], %2, [%3];"
        :: "r"(bufb + B_OFF), "l"(srcB), "r"(16384u), "r"(mbar) : "memory");
}

__global__ void __launch_bounds__(256, 1) gemm_kernel(float* __restrict__ y) {
    extern __shared__ __align__(1024) char smem[];
    const uint32_t sb = smem_u32(smem);
    const int tid = threadIdx.x, lane = tid & 31, wid = tid >> 5;
    const int wm = wid >> 1, wn = wid & 1;          // warp grid 4(M) x 2(N)
    const int n0 = blockIdx.x * 64;
    const int m0 = blockIdx.y * 128;

    if (tid < 4)
        asm volatile("mbarrier.init.shared.b64 [%0], 1;"
                     :: "r"(sb + tid * 8) : "memory");
    __syncthreads();
    if (tid == 0) {
        tma_chunk(sb + SM_TILES + 0 * BUF, sb + 0,  0, m0, n0);
        tma_chunk(sb + SM_TILES + 1 * BUF, sb + 8,  1, m0, n0);
        tma_chunk(sb + SM_TILES + 2 * BUF, sb + 16, 2, m0, n0);
        tma_chunk(sb + SM_TILES + 3 * BUF, sb + 24, 3, m0, n0);
    }

    float acc[2][4][4];
    #pragma unroll
    for (int i = 0; i < 2; ++i)
        #pragma unroll
        for (int j = 0; j < 4; ++j)
            #pragma unroll
            for (int q = 0; q < 4; ++q) acc[i][j][q] = 0.f;

    const int rl = lane & 15;
    const uint32_t kh16 = (uint32_t)(lane >> 4) * 16;
    const uint32_t arow0 = (uint32_t)(wm * 32 + rl) * 128;
    const uint32_t arow1 = arow0 + 16 * 128;
    const uint32_t brow0 = (uint32_t)(wn * 32 + rl) * 128;
    const uint32_t brow1 = brow0 + 16 * 128;

    for (int c = 0; c < NC; ++c) {
        const int b = c & 3;
        MBAR_WAIT(sb + b * 8, (c >> 2) & 1);
        const uint32_t bb = sb + SM_TILES + b * BUF;

        #pragma unroll
        for (int ks = 0; ks < 8; ++ks) {
            const uint32_t sub_a = bb + (ks >> 2) * A_SUB;
            const uint32_t sub_b = bb + B_OFF + (ks >> 2) * B_SUB;
            const uint32_t kb = (uint32_t)(ks & 3) * 32 + kh16;
            uint32_t ah[2][4], bh[2][4];
            ldsm4(ah[0], sub_a + SW128(arow0 + kb));
            ldsm4(ah[1], sub_a + SW128(arow1 + kb));
            ldsm4(bh[0], sub_b + SW128(brow0 + kb));
            ldsm4(bh[1], sub_b + SW128(brow1 + kb));
            #pragma unroll
            for (int mi = 0; mi < 2; ++mi)
                #pragma unroll
                for (int nj = 0; nj < 2; ++nj) {
                    mma16816(acc[mi][nj*2+0], ah[mi], bh[nj][0], bh[nj][2]);
                    mma16816(acc[mi][nj*2+1], ah[mi], bh[nj][1], bh[nj][3]);
                }
        }
        // Block barrier + dual reissue every 2 chunks: after odd chunk c,
        // buffers holding chunks c-1 and c are free for chunks c+3, c+4.
        if (c & 1) {
            __syncthreads();
            if (tid == 0) {
                if (c + 3 < NC)
                    tma_chunk(sb + SM_TILES + ((c + 3) & 3) * BUF,
                              sb + ((c + 3) & 3) * 8, c + 3, m0, n0);
                if (c + 4 < NC)
                    tma_chunk(sb + SM_TILES + ((c + 4) & 3) * BUF,
                              sb + ((c + 4) & 3) * 8, c + 4, m0, n0);
            }
        }
    }

    #pragma unroll
    for (int mi = 0; mi < 2; ++mi) {
        const int row0 = m0 + wm * 32 + mi * 16 + (lane >> 2);
        #pragma unroll
        for (int nb = 0; nb < 4; ++nb) {
            const int col = n0 + wn * 32 + nb * 8 + (lane & 3) * 2;
            *reinterpret_cast<float2*>(y + (size_t)row0 * O_DIM + col) =
                make_float2(acc[mi][nb][0], acc[mi][nb][1]);
            *reinterpret_cast<float2*>(y + (size_t)(row0 + 8) * O_DIM + col) =
                make_float2(acc[mi][nb][2], acc[mi][nb][3]);
        }
    }
}

// ============================================================================
extern "C" void kernel_launch(void* const* d_in, const int* in_sizes, int n_in,
                              void* d_out, int out_size) {
    const float* x    = (const float*)d_in[0];
    const float* w    = (const float*)d_in[1];
    const int*   flip = (const int*)d_in[2];   // JAX x64 disabled -> int32
    const float* vals = (const float*)d_in[3];
    float*       y    = (float*)d_out;
    const int nflip = in_sizes[2];

    stage1_kernel<<<NB_WIN + NB_CX + NB_CW, 256>>>(
        reinterpret_cast<const float4*>(x), reinterpret_cast<const float4*>(w),
        flip, nflip);
    scatter_kernel<<<(nflip + 2047) / 2048, 256>>>(flip, vals, nflip);

    cudaFuncSetAttribute(gemm_kernel, cudaFuncAttributeMaxDynamicSharedMemorySize,
                         GEMM_SMEM);
    gemm_kernel<<<dim3(O_DIM / 64, B_ROWS / 128, 1), 256, GEMM_SMEM>>>(y);
}